// round 5
// baseline (speedup 1.0000x reference)
#include <cuda_runtime.h>
#include <cstdint>

#define HIDDEN 2048
#define INTER  5504
#define TSTEPS 4
#define MROWS  4096   /* T*BSZ*SEQ */
#define BSROWS 1024   /* BSZ*SEQ */

#define STAGES      3
#define STAGE_BYTES 32768                  /* A 16KB + B 16KB */
#define DYN_SMEM    (STAGES * STAGE_BYTES) /* 96 KB, 1 CTA/SM */

// ---------------- scratch (device globals; no allocation allowed) ----------
__device__ float g_X [(size_t)MROWS * HIDDEN];
__device__ float g_WG[(size_t)INTER * HIDDEN];
__device__ float g_WU[(size_t)INTER * HIDDEN];
__device__ float g_WD[(size_t)HIDDEN * INTER];
__device__ float g_G [(size_t)MROWS * INTER];
__device__ float g_U [(size_t)MROWS * INTER];

// ---------------- helpers ----------------------------------------------------
__device__ __forceinline__ uint32_t smem_u32(const void* p) {
    uint32_t a;
    asm("{ .reg .u64 t; cvta.to.shared.u64 t, %1; cvt.u32.u64 %0, t; }" : "=r"(a) : "l"(p));
    return a;
}
__device__ __forceinline__ uint32_t f2tf32(float x) {
    uint32_t r; asm("cvt.rna.tf32.f32 %0, %1;" : "=r"(r) : "f"(x)); return r;
}
__device__ __forceinline__ float roundtf(float x) { return __uint_as_float(f2tf32(x)); }

#define CP_ASYNC16(dst, src) \
    asm volatile("cp.async.cg.shared.global [%0], [%1], 16;" :: "r"(dst), "l"(src))
#define CP_COMMIT() asm volatile("cp.async.commit_group;" ::: "memory")
#define CP_WAIT1()  asm volatile("cp.async.wait_group 1;"  ::: "memory")

// ldmatrix x4 on 4-byte words: thread gets word (lane%4) of row (lane/4) per matrix.
#define LDSM_X4(r0, r1, r2, r3, addr) \
    asm volatile("ldmatrix.sync.aligned.m8n8.x4.shared.b16 {%0,%1,%2,%3}, [%4];" \
                 : "=r"(r0), "=r"(r1), "=r"(r2), "=r"(r3) : "r"(addr))

__device__ __forceinline__ void mma_tf32(float* d, const uint32_t* a, const uint32_t* b) {
    asm volatile(
        "mma.sync.aligned.m16n8k8.row.col.f32.tf32.tf32.f32 "
        "{%0,%1,%2,%3}, {%4,%5,%6,%7}, {%8,%9}, {%0,%1,%2,%3};\n"
        : "+f"(d[0]), "+f"(d[1]), "+f"(d[2]), "+f"(d[3])
        : "r"(a[0]), "r"(a[1]), "r"(a[2]), "r"(a[3]), "r"(b[0]), "r"(b[1]));
}

// ---------------- GEMM: C[m,n] = sum_k A[m,k]*B[n,k] ------------------------
// A: M x K row-major, B: N x K row-major, both PRE-ROUNDED to tf32 (rna).
// 512 threads, 16 warps in 4x4, warp tile 32x32, 3-stage cp.async, LDSM frags.
// Requires M%128==0 (grid.y), N%128==0 (grid.x), K%32==0.
__global__ void __launch_bounds__(512, 1)
gemm_tn(const float* __restrict__ A, const float* __restrict__ B,
        float* __restrict__ C, int K, int N)
{
    extern __shared__ __align__(16) uint8_t smraw[];
    const uint32_t sb = smem_u32(smraw);

    const int tid  = threadIdx.x;
    const int lane = tid & 31;
    const int warp = tid >> 5;
    const int wm   = warp & 3;   // 4 warp rows of 32
    const int wn   = warp >> 2;  // 4 warp cols of 32

    // cp.async fill mapping: 512 threads, 4 chunks each (2 A + 2 B)
    const int r = tid >> 3;      // 0..63 : row within group of 64
    const int c = tid & 7;       // 0..7  : 16B (k4) chunk within 128B row

    // LDSM per-lane selectors (mapping verified in R4, same rel_err):
    //  A matrices: (m = base + [0|8] + lane&7, k4 = ks*2 + lane>>4)
    //  B matrices: (n = base + [0|8] + lane&7, k4 = ks*2 + (lane>>3)&1)
    const int rsel   = lane & 7;
    const int a_k4hi = lane >> 4;
    const int a_moff = ((lane >> 3) & 1) << 3;
    const int b_k4lo = (lane >> 3) & 1;
    const int b_noff = (lane >> 4) << 3;
    const int mrowA  = wm * 32 + a_moff + rsel;
    const int nrowB  = wn * 32 + b_noff + rsel;

    const size_t mBase = (size_t)blockIdx.y * 128;
    const size_t nBase = (size_t)blockIdx.x * 128;
    const int NK = K >> 5;

    const float* Ag = A + (mBase + (size_t)r) * (size_t)K + (size_t)c * 4;
    const float* Bg = B + (nBase + (size_t)r) * (size_t)K + (size_t)c * 4;

    // smem stage: A atoms [k4(0..7)][m(0..127)] float4 at slot m^k4; B at +16KB.
    auto fill = [&](int s, int kt) {
        const uint32_t abase = sb + s * STAGE_BYTES;
        const uint32_t bbase = abase + 16384;
        const float* Ak = Ag + (size_t)kt * 32;
        const float* Bk = Bg + (size_t)kt * 32;
        #pragma unroll
        for (int j = 0; j < 2; ++j) {
            const int m = j * 64 + r;
            const uint32_t slot = (uint32_t)(c * 128 + (m ^ c)) << 4;
            CP_ASYNC16(abase + slot, Ak + (size_t)(j * 64) * K);
            CP_ASYNC16(bbase + slot, Bk + (size_t)(j * 64) * K);
        }
    };

    fill(0, 0); CP_COMMIT();
    fill(1, 1); CP_COMMIT();

    float acc[2][4][4];
    #pragma unroll
    for (int i = 0; i < 2; ++i)
        #pragma unroll
        for (int j = 0; j < 4; ++j)
            #pragma unroll
            for (int q = 0; q < 4; ++q) acc[i][j][q] = 0.f;

    for (int kt = 0; kt < NK; ++kt) {
        CP_WAIT1();          // stage kt resident
        __syncthreads();     // stage (kt+2)%3 fully consumed by all warps

        if (kt + 2 < NK) fill((kt + 2) % STAGES, kt + 2);
        CP_COMMIT();         // empty tail groups keep numbering

        const uint32_t abase = sb + (kt % STAGES) * STAGE_BYTES;
        const uint32_t bbase = abase + 16384;

        #pragma unroll
        for (int ks = 0; ks < 4; ++ks) {
            const uint32_t ak4 = (uint32_t)(ks * 2 + a_k4hi);
            const uint32_t bk4 = (uint32_t)(ks * 2 + b_k4lo);

            uint32_t af[2][4];
            #pragma unroll
            for (int im = 0; im < 2; ++im) {
                const uint32_t m = (uint32_t)(mrowA + im * 16);
                const uint32_t addr = abase + (ak4 << 11) + (((m ^ ak4) & 127u) << 4);
                LDSM_X4(af[im][0], af[im][1], af[im][2], af[im][3], addr);
            }
            uint32_t bf[4][2];
            #pragma unroll
            for (int p = 0; p < 2; ++p) {
                const uint32_t n = (uint32_t)(nrowB + p * 16);
                const uint32_t addr = bbase + (bk4 << 11) + (((n ^ bk4) & 127u) << 4);
                LDSM_X4(bf[2 * p][0], bf[2 * p][1], bf[2 * p + 1][0], bf[2 * p + 1][1], addr);
            }
            #pragma unroll
            for (int im = 0; im < 2; ++im)
                #pragma unroll
                for (int jn = 0; jn < 4; ++jn)
                    mma_tf32(acc[im][jn], af[im], bf[jn]);
        }
    }

    // Epilogue: fragment layout -> global (float2 per half-row).
    const int g  = lane >> 2;
    const int q2 = (lane & 3) * 2;
    #pragma unroll
    for (int im = 0; im < 2; ++im) {
        const size_t row0 = mBase + wm * 32 + im * 16 + g;
        #pragma unroll
        for (int jn = 0; jn < 4; ++jn) {
            const size_t col0 = nBase + wn * 32 + jn * 8 + q2;
            *(float2*)&C[row0 * (size_t)N + col0] =
                make_float2(acc[im][jn][0], acc[im][jn][1]);
            *(float2*)&C[(row0 + 8) * (size_t)N + col0] =
                make_float2(acc[im][jn][2], acc[im][jn][3]);
        }
    }
}

// ---------------- prepass: tf32-rna rounding --------------------------------
__global__ void round_copy_k(const float* __restrict__ src, float* __restrict__ dst, long n4)
{
    long i = (long)blockIdx.x * blockDim.x + threadIdx.x;
    if (i >= n4) return;
    float4 v = *(const float4*)(src + i * 4);
    *(float4*)(dst + i * 4) =
        make_float4(roundtf(v.x), roundtf(v.y), roundtf(v.z), roundtf(v.w));
}

// ---------------- combine: cumsum/silu/delta + closed-form Hadamard ---------
__global__ void combine_kernel()
{
    const size_t total  = (size_t)BSROWS * INTER;
    const size_t stride = total;
    size_t idx = (size_t)blockIdx.x * blockDim.x + threadIdx.x;
    if (idx >= total) return;

    float gv[TSTEPS], uv[TSTEPS];
    #pragma unroll
    for (int t = 0; t < TSTEPS; ++t) {
        gv[t] = g_G[idx + (size_t)t * stride];
        uv[t] = g_U[idx + (size_t)t * stride];
    }

    float X = 0.f, Yprev = 0.f, SB = 0.f;
    float Av[TSTEPS];
    #pragma unroll
    for (int t = 0; t < TSTEPS; ++t) {
        X += gv[t];
        const float Y = X / (1.f + expf(-X));  // silu
        Av[t] = Y - Yprev;
        Yprev = Y;
        SB += uv[t];
    }
    const float SA = Yprev;  // telescoping: sum_t A[t] = Y[T-1]

    #pragma unroll
    for (int t = 0; t < TSTEPS; ++t)
        g_G[idx + (size_t)t * stride] = roundtf(0.5f * (Av[t] * SB + uv[t] * SA));
}

// ---------------- launch -----------------------------------------------------
extern "C" void kernel_launch(void* const* d_in, const int* in_sizes, int n_in,
                              void* d_out, int out_size)
{
    const float* x      = (const float*)d_in[0];
    const float* w_gate = (const float*)d_in[1];
    const float* w_up   = (const float*)d_in[2];
    const float* w_down = (const float*)d_in[3];
    float* out = (float*)d_out;
    (void)in_sizes; (void)n_in; (void)out_size;

    float *dX, *dWG, *dWU, *dWD, *dG, *dU;
    cudaGetSymbolAddress((void**)&dX,  g_X);
    cudaGetSymbolAddress((void**)&dWG, g_WG);
    cudaGetSymbolAddress((void**)&dWU, g_WU);
    cudaGetSymbolAddress((void**)&dWD, g_WD);
    cudaGetSymbolAddress((void**)&dG,  g_G);
    cudaGetSymbolAddress((void**)&dU,  g_U);

    cudaFuncSetAttribute(gemm_tn, cudaFuncAttributeMaxDynamicSharedMemorySize, DYN_SMEM);

    // Prepass: tf32-rna round operands once (GEMM inner loop is CVT-free).
    {
        long n4 = (long)MROWS * HIDDEN / 4;
        round_copy_k<<<(unsigned)((n4 + 255) / 256), 256>>>(x, dX, n4);
        long w4 = (long)INTER * HIDDEN / 4;
        round_copy_k<<<(unsigned)((w4 + 255) / 256), 256>>>(w_gate, dWG, w4);
        round_copy_k<<<(unsigned)((w4 + 255) / 256), 256>>>(w_up,   dWU, w4);
        round_copy_k<<<(unsigned)((w4 + 255) / 256), 256>>>(w_down, dWD, w4);
    }

    // Gate / up projections: (4096 x 5504) = x(4096x2048) @ W^T
    {
        dim3 grid(INTER / 128, MROWS / 128);   // 43 x 32
        gemm_tn<<<grid, 512, DYN_SMEM>>>(dX, dWG, dG, HIDDEN, INTER);
        gemm_tn<<<grid, 512, DYN_SMEM>>>(dX, dWU, dU, HIDDEN, INTER);
    }

    // Combine (C -> g_G, rounded for the next GEMM).
    {
        size_t total = (size_t)BSROWS * INTER;
        combine_kernel<<<(unsigned)((total + 255) / 256), 256>>>();
    }

    // Down projection: (4096 x 2048) = C(4096x5504) @ w_down^T
    {
        dim3 grid(HIDDEN / 128, MROWS / 128);  // 16 x 32
        gemm_tn<<<grid, 512, DYN_SMEM>>>(dG, dWD, out, INTER, HIDDEN);
    }
}

// round 6
// speedup vs baseline: 1.9292x; 1.9292x over previous
#include <cuda_runtime.h>
#include <cstdint>

#define HIDDEN 2048
#define INTER  5504
#define TSTEPS 4
#define MROWS  4096   /* T*BSZ*SEQ */
#define BSROWS 1024   /* BSZ*SEQ */

#define DYN_SMEM 65536   /* 2 buffers x (A 16KB + B 16KB) */

// ---------------- scratch (device globals; no allocation allowed) ----------
__device__ float g_X [(size_t)MROWS * HIDDEN];
__device__ float g_WG[(size_t)INTER * HIDDEN];
__device__ float g_WU[(size_t)INTER * HIDDEN];
__device__ float g_WD[(size_t)HIDDEN * INTER];
__device__ float g_G [(size_t)MROWS * INTER];
__device__ float g_U [(size_t)MROWS * INTER];

// ---------------- helpers ----------------------------------------------------
__device__ __forceinline__ uint32_t smem_u32(const void* p) {
    uint32_t a;
    asm("{ .reg .u64 t; cvta.to.shared.u64 t, %1; cvt.u32.u64 %0, t; }" : "=r"(a) : "l"(p));
    return a;
}
__device__ __forceinline__ uint32_t f2tf32(float x) {
    uint32_t r; asm("cvt.rna.tf32.f32 %0, %1;" : "=r"(r) : "f"(x)); return r;
}
__device__ __forceinline__ float roundtf(float x) { return __uint_as_float(f2tf32(x)); }

// ldmatrix x4 on 4-byte words: thread gets word (lane%4) of row (lane/4) per matrix.
#define LDSM_X4(r0, r1, r2, r3, addr) \
    asm volatile("ldmatrix.sync.aligned.m8n8.x4.shared.b16 {%0,%1,%2,%3}, [%4];" \
                 : "=r"(r0), "=r"(r1), "=r"(r2), "=r"(r3) : "r"(addr))

__device__ __forceinline__ void mma_tf32(float* d, const uint32_t* a, const uint32_t* b) {
    asm volatile(
        "mma.sync.aligned.m16n8k8.row.col.f32.tf32.tf32.f32 "
        "{%0,%1,%2,%3}, {%4,%5,%6,%7}, {%8,%9}, {%0,%1,%2,%3};\n"
        : "+f"(d[0]), "+f"(d[1]), "+f"(d[2]), "+f"(d[3])
        : "r"(a[0]), "r"(a[1]), "r"(a[2]), "r"(a[3]), "r"(b[0]), "r"(b[1]));
}

// ---------------- GEMM: C[m,n] = sum_k A[m,k]*B[n,k] ------------------------
// A: M x K row-major, B: N x K row-major, both PRE-ROUNDED to tf32 (rna).
// 256 threads, 8 warps (2x4), warp tile 64x32, register-prefetched globals,
// double-buffered smem (one __syncthreads per K-tile), LDSM fragment loads.
// Requires M%128==0 (grid.y), N%128==0 (grid.x), K%32==0.
__global__ void __launch_bounds__(256, 1)
gemm_tn(const float* __restrict__ A, const float* __restrict__ B,
        float* __restrict__ C, int K, int N)
{
    extern __shared__ __align__(16) uint8_t smraw[];
    uint4* sm = reinterpret_cast<uint4*>(smraw);      // sm[buf*2048 .. ]
    const uint32_t sb = smem_u32(smraw);

    const int tid  = threadIdx.x;
    const int lane = tid & 31;
    const int warp = tid >> 5;
    const int wm   = warp & 1;   // 2 warp rows of 64
    const int wn   = warp >> 1;  // 4 warp cols of 32

    // global-load mapping
    const int r = tid >> 3;      // 0..31 : row within group of 32
    const int c = tid & 7;       // 0..7  : 16B (k4) chunk within 128B row

    // LDSM per-lane selectors (verified bit-exact in R4):
    const int rsel   = lane & 7;
    const int a_k4hi = lane >> 4;
    const int a_moff = ((lane >> 3) & 1) << 3;
    const int b_k4lo = (lane >> 3) & 1;
    const int b_noff = (lane >> 4) << 3;
    const int mrowA  = wm * 64 + a_moff + rsel;
    const int nrowB  = wn * 32 + b_noff + rsel;

    const size_t mBase = (size_t)blockIdx.y * 128;
    const size_t nBase = (size_t)blockIdx.x * 128;
    const int NK = K >> 5;

    const float* Ag = A + (mBase + (size_t)r) * (size_t)K + (size_t)c * 4;
    const float* Bg = B + (nBase + (size_t)r) * (size_t)K + (size_t)c * 4;

    float4 pa[4], pb[4];

    auto ldg_tile = [&](int kt) {
        const float* Ak = Ag + (size_t)kt * 32;
        const float* Bk = Bg + (size_t)kt * 32;
        #pragma unroll
        for (int j = 0; j < 4; ++j) {
            pa[j] = *(const float4*)(Ak + (size_t)(j * 32) * K);
            pb[j] = *(const float4*)(Bk + (size_t)(j * 32) * K);
        }
    };
    // smem buffer layout: A atoms [k4(0..7)][m(0..127)] uint4 at slot m^k4; B at +1024.
    auto sts_tile = [&](int buf) {
        uint4* As = sm + buf * 2048;
        uint4* Bs = As + 1024;
        #pragma unroll
        for (int j = 0; j < 4; ++j) {
            const int m = j * 32 + r;
            const int slot = c * 128 + (m ^ c);
            As[slot] = *reinterpret_cast<uint4*>(&pa[j]);
            Bs[slot] = *reinterpret_cast<uint4*>(&pb[j]);
        }
    };

    float acc[4][4][4];
    #pragma unroll
    for (int i = 0; i < 4; ++i)
        #pragma unroll
        for (int j = 0; j < 4; ++j)
            #pragma unroll
            for (int q = 0; q < 4; ++q) acc[i][j][q] = 0.f;

    // prologue
    ldg_tile(0);
    sts_tile(0);
    if (NK > 1) ldg_tile(1);
    __syncthreads();

    for (int kt = 0; kt < NK; ++kt) {
        // Store tile kt+1 into the other buffer (its readers finished at kt-1's
        // barrier), then issue tile kt+2's global loads for deep MLP.
        if (kt + 1 < NK) {
            sts_tile((kt + 1) & 1);
            if (kt + 2 < NK) ldg_tile(kt + 2);
        }

        const uint32_t abase = sb + (uint32_t)((kt & 1) * 32768);
        const uint32_t bbase = abase + 16384;

        #pragma unroll
        for (int ks = 0; ks < 4; ++ks) {
            const uint32_t ak4 = (uint32_t)(ks * 2 + a_k4hi);
            const uint32_t bk4 = (uint32_t)(ks * 2 + b_k4lo);

            uint32_t af[4][4];
            #pragma unroll
            for (int im = 0; im < 4; ++im) {
                const uint32_t m = (uint32_t)(mrowA + im * 16);
                const uint32_t addr = abase + (ak4 << 11) + (((m ^ ak4) & 127u) << 4);
                LDSM_X4(af[im][0], af[im][1], af[im][2], af[im][3], addr);
            }
            uint32_t bf[4][2];
            #pragma unroll
            for (int p = 0; p < 2; ++p) {
                const uint32_t n = (uint32_t)(nrowB + p * 16);
                const uint32_t addr = bbase + (bk4 << 11) + (((n ^ bk4) & 127u) << 4);
                LDSM_X4(bf[2 * p][0], bf[2 * p][1], bf[2 * p + 1][0], bf[2 * p + 1][1], addr);
            }
            #pragma unroll
            for (int im = 0; im < 4; ++im)
                #pragma unroll
                for (int jn = 0; jn < 4; ++jn)
                    mma_tf32(acc[im][jn], af[im], bf[jn]);
        }
        __syncthreads();
    }

    // Epilogue: fragment layout -> global (float2 per half-row).
    const int g  = lane >> 2;
    const int q2 = (lane & 3) * 2;
    #pragma unroll
    for (int im = 0; im < 4; ++im) {
        const size_t row0 = mBase + wm * 64 + im * 16 + g;
        #pragma unroll
        for (int jn = 0; jn < 4; ++jn) {
            const size_t col0 = nBase + wn * 32 + jn * 8 + q2;
            *(float2*)&C[row0 * (size_t)N + col0] =
                make_float2(acc[im][jn][0], acc[im][jn][1]);
            *(float2*)&C[(row0 + 8) * (size_t)N + col0] =
                make_float2(acc[im][jn][2], acc[im][jn][3]);
        }
    }
}

// ---------------- prepass: tf32-rna rounding --------------------------------
__global__ void round_copy_k(const float* __restrict__ src, float* __restrict__ dst, long n4)
{
    long i = (long)blockIdx.x * blockDim.x + threadIdx.x;
    if (i >= n4) return;
    float4 v = *(const float4*)(src + i * 4);
    *(float4*)(dst + i * 4) =
        make_float4(roundtf(v.x), roundtf(v.y), roundtf(v.z), roundtf(v.w));
}

// ---------------- combine: cumsum/silu/delta + closed-form Hadamard ---------
__global__ void combine_kernel()
{
    const size_t total  = (size_t)BSROWS * INTER;
    const size_t stride = total;
    size_t idx = (size_t)blockIdx.x * blockDim.x + threadIdx.x;
    if (idx >= total) return;

    float gv[TSTEPS], uv[TSTEPS];
    #pragma unroll
    for (int t = 0; t < TSTEPS; ++t) {
        gv[t] = g_G[idx + (size_t)t * stride];
        uv[t] = g_U[idx + (size_t)t * stride];
    }

    float X = 0.f, Yprev = 0.f, SB = 0.f;
    float Av[TSTEPS];
    #pragma unroll
    for (int t = 0; t < TSTEPS; ++t) {
        X += gv[t];
        const float Y = X / (1.f + expf(-X));  // silu
        Av[t] = Y - Yprev;
        Yprev = Y;
        SB += uv[t];
    }
    const float SA = Yprev;  // telescoping: sum_t A[t] = Y[T-1]

    #pragma unroll
    for (int t = 0; t < TSTEPS; ++t)
        g_G[idx + (size_t)t * stride] = roundtf(0.5f * (Av[t] * SB + uv[t] * SA));
}

// ---------------- launch -----------------------------------------------------
extern "C" void kernel_launch(void* const* d_in, const int* in_sizes, int n_in,
                              void* d_out, int out_size)
{
    const float* x      = (const float*)d_in[0];
    const float* w_gate = (const float*)d_in[1];
    const float* w_up   = (const float*)d_in[2];
    const float* w_down = (const float*)d_in[3];
    float* out = (float*)d_out;
    (void)in_sizes; (void)n_in; (void)out_size;

    float *dX, *dWG, *dWU, *dWD, *dG, *dU;
    cudaGetSymbolAddress((void**)&dX,  g_X);
    cudaGetSymbolAddress((void**)&dWG, g_WG);
    cudaGetSymbolAddress((void**)&dWU, g_WU);
    cudaGetSymbolAddress((void**)&dWD, g_WD);
    cudaGetSymbolAddress((void**)&dG,  g_G);
    cudaGetSymbolAddress((void**)&dU,  g_U);

    cudaFuncSetAttribute(gemm_tn, cudaFuncAttributeMaxDynamicSharedMemorySize, DYN_SMEM);

    // Prepass: tf32-rna round operands once (GEMM inner loop is CVT-free).
    {
        long n4 = (long)MROWS * HIDDEN / 4;
        round_copy_k<<<(unsigned)((n4 + 255) / 256), 256>>>(x, dX, n4);
        long w4 = (long)INTER * HIDDEN / 4;
        round_copy_k<<<(unsigned)((w4 + 255) / 256), 256>>>(w_gate, dWG, w4);
        round_copy_k<<<(unsigned)((w4 + 255) / 256), 256>>>(w_up,   dWU, w4);
        round_copy_k<<<(unsigned)((w4 + 255) / 256), 256>>>(w_down, dWD, w4);
    }

    // Gate / up projections: (4096 x 5504) = x(4096x2048) @ W^T
    {
        dim3 grid(INTER / 128, MROWS / 128);   // 43 x 32
        gemm_tn<<<grid, 256, DYN_SMEM>>>(dX, dWG, dG, HIDDEN, INTER);
        gemm_tn<<<grid, 256, DYN_SMEM>>>(dX, dWU, dU, HIDDEN, INTER);
    }

    // Combine (C -> g_G, rounded for the next GEMM).
    {
        size_t total = (size_t)BSROWS * INTER;
        combine_kernel<<<(unsigned)((total + 255) / 256), 256>>>();
    }

    // Down projection: (4096 x 2048) = C(4096x5504) @ w_down^T
    {
        dim3 grid(HIDDEN / 128, MROWS / 128);  // 16 x 32
        gemm_tn<<<grid, 256, DYN_SMEM>>>(dG, dWD, out, INTER, HIDDEN);
    }
}

// round 7
// speedup vs baseline: 2.2444x; 1.1634x over previous
#include <cuda_runtime.h>
#include <cstdint>

#define HIDDEN    2048
#define INTER     5504
#define INTER_PAD 5632   /* 22 * 256 */
#define TSTEPS    4
#define MROWS     4096   /* T*BSZ*SEQ */
#define BSROWS    1024   /* BSZ*SEQ */

#define BUF_BYTES 49152  /* A 16KB + B 32KB */
#define DYN_SMEM  (2 * BUF_BYTES)

// ---------------- scratch (device globals; no allocation allowed) ----------
__device__ float g_X [(size_t)MROWS * HIDDEN];
__device__ float g_WG[(size_t)INTER_PAD * HIDDEN];
__device__ float g_WU[(size_t)INTER_PAD * HIDDEN];
__device__ float g_WD[(size_t)HIDDEN * INTER_PAD];
__device__ float g_G [(size_t)MROWS * INTER_PAD];
__device__ float g_U [(size_t)MROWS * INTER_PAD];

// ---------------- helpers ----------------------------------------------------
__device__ __forceinline__ uint32_t smem_u32(const void* p) {
    uint32_t a;
    asm("{ .reg .u64 t; cvta.to.shared.u64 t, %1; cvt.u32.u64 %0, t; }" : "=r"(a) : "l"(p));
    return a;
}
__device__ __forceinline__ uint32_t f2tf32(float x) {
    uint32_t r; asm("cvt.rna.tf32.f32 %0, %1;" : "=r"(r) : "f"(x)); return r;
}
__device__ __forceinline__ float roundtf(float x) { return __uint_as_float(f2tf32(x)); }

// ldmatrix x4 on 4-byte words: thread gets word (lane%4) of row (lane/4) per matrix.
#define LDSM_X4(r0, r1, r2, r3, addr) \
    asm volatile("ldmatrix.sync.aligned.m8n8.x4.shared.b16 {%0,%1,%2,%3}, [%4];" \
                 : "=r"(r0), "=r"(r1), "=r"(r2), "=r"(r3) : "r"(addr))

__device__ __forceinline__ void mma_tf32(float* d, const uint32_t* a, const uint32_t* b) {
    asm volatile(
        "mma.sync.aligned.m16n8k8.row.col.f32.tf32.tf32.f32 "
        "{%0,%1,%2,%3}, {%4,%5,%6,%7}, {%8,%9}, {%0,%1,%2,%3};\n"
        : "+f"(d[0]), "+f"(d[1]), "+f"(d[2]), "+f"(d[3])
        : "r"(a[0]), "r"(a[1]), "r"(a[2]), "r"(a[3]), "r"(b[0]), "r"(b[1]));
}

// ---------------- GEMM: C[m,n] = sum_k A[m,k]*B[n,k] ------------------------
// A: M x K row-major, B: N x K row-major, both PRE-ROUNDED to tf32 (rna).
// Block tile 128x256, 256 threads, 8 warps (2x4), warp tile 64x64.
// Register-prefetched globals, double-buffered smem, one barrier per K-tile,
// ldmatrix fragment loads. Requires M%128==0, N%256==0, K%32==0.
__global__ void __launch_bounds__(256, 1)
gemm_tn(const float* __restrict__ A, const float* __restrict__ B,
        float* __restrict__ C, int K, int N)
{
    extern __shared__ __align__(16) uint8_t smraw[];
    uint4* sm = reinterpret_cast<uint4*>(smraw);
    const uint32_t sb = smem_u32(smraw);

    const int tid  = threadIdx.x;
    const int lane = tid & 31;
    const int warp = tid >> 5;
    const int wm   = warp & 1;   // 2 warp rows of 64
    const int wn   = warp >> 1;  // 4 warp cols of 64

    // global-load mapping
    const int r = tid >> 3;      // 0..31 : row within group of 32
    const int c = tid & 7;       // 0..7  : 16B (k4) chunk within 128B row

    // LDSM per-lane selectors (mapping verified bit-exact in R4/R6):
    const int rsel   = lane & 7;
    const int a_k4hi = lane >> 4;
    const int a_moff = ((lane >> 3) & 1) << 3;
    const int b_k4lo = (lane >> 3) & 1;
    const int b_noff = (lane >> 4) << 3;
    const int mrowA  = wm * 64 + a_moff + rsel;
    const int nrowB  = wn * 64 + b_noff + rsel;

    const size_t mBase = (size_t)blockIdx.y * 128;
    const size_t nBase = (size_t)blockIdx.x * 256;
    const int NK = K >> 5;

    const float* Ag = A + (mBase + (size_t)r) * (size_t)K + (size_t)c * 4;
    const float* Bg = B + (nBase + (size_t)r) * (size_t)K + (size_t)c * 4;

    float4 pa[4], pb[8];

    auto ldg_tile = [&](int kt) {
        const float* Ak = Ag + (size_t)kt * 32;
        const float* Bk = Bg + (size_t)kt * 32;
        #pragma unroll
        for (int j = 0; j < 4; ++j)
            pa[j] = *(const float4*)(Ak + (size_t)(j * 32) * K);
        #pragma unroll
        for (int j = 0; j < 8; ++j)
            pb[j] = *(const float4*)(Bk + (size_t)(j * 32) * K);
    };
    // smem buffer: A atoms [k4(0..7)][m(0..127)] uint4 at slot m^k4;
    //              B atoms [k4(0..7)][n(0..255)] uint4 at slot n^k4 (at +16KB).
    auto sts_tile = [&](int buf) {
        uint4* As = sm + buf * (BUF_BYTES / 16);
        uint4* Bs = As + 1024;
        #pragma unroll
        for (int j = 0; j < 4; ++j) {
            const int m = j * 32 + r;
            As[c * 128 + (m ^ c)] = *reinterpret_cast<uint4*>(&pa[j]);
        }
        #pragma unroll
        for (int j = 0; j < 8; ++j) {
            const int n = j * 32 + r;
            Bs[c * 256 + (n ^ c)] = *reinterpret_cast<uint4*>(&pb[j]);
        }
    };

    float acc[4][8][4];
    #pragma unroll
    for (int i = 0; i < 4; ++i)
        #pragma unroll
        for (int j = 0; j < 8; ++j)
            #pragma unroll
            for (int q = 0; q < 4; ++q) acc[i][j][q] = 0.f;

    // prologue
    ldg_tile(0);
    sts_tile(0);
    if (NK > 1) ldg_tile(1);
    __syncthreads();

    for (int kt = 0; kt < NK; ++kt) {
        if (kt + 1 < NK) {
            sts_tile((kt + 1) & 1);
            if (kt + 2 < NK) ldg_tile(kt + 2);
        }

        const uint32_t abase = sb + (uint32_t)((kt & 1) * BUF_BYTES);
        const uint32_t bbase = abase + 16384;

        #pragma unroll
        for (int ks = 0; ks < 4; ++ks) {
            const uint32_t ak4 = (uint32_t)(ks * 2 + a_k4hi);
            const uint32_t bk4 = (uint32_t)(ks * 2 + b_k4lo);

            uint32_t af[4][4];
            #pragma unroll
            for (int im = 0; im < 4; ++im) {
                const uint32_t m = (uint32_t)(mrowA + im * 16);
                const uint32_t addr = abase + (ak4 << 11) + (((m ^ ak4) & 127u) << 4);
                LDSM_X4(af[im][0], af[im][1], af[im][2], af[im][3], addr);
            }
            uint32_t bf[8][2];
            #pragma unroll
            for (int p = 0; p < 4; ++p) {
                const uint32_t n = (uint32_t)(nrowB + p * 16);
                const uint32_t addr = bbase + (bk4 << 12) + (((n ^ bk4) & 255u) << 4);
                LDSM_X4(bf[2 * p][0], bf[2 * p][1], bf[2 * p + 1][0], bf[2 * p + 1][1], addr);
            }
            #pragma unroll
            for (int im = 0; im < 4; ++im)
                #pragma unroll
                for (int jn = 0; jn < 8; ++jn)
                    mma_tf32(acc[im][jn], af[im], bf[jn]);
        }
        __syncthreads();
    }

    // Epilogue: fragment layout -> global (float2 per half-row).
    const int g  = lane >> 2;
    const int q2 = (lane & 3) * 2;
    #pragma unroll
    for (int im = 0; im < 4; ++im) {
        const size_t row0 = mBase + wm * 64 + im * 16 + g;
        #pragma unroll
        for (int jn = 0; jn < 8; ++jn) {
            const size_t col0 = nBase + wn * 64 + jn * 8 + q2;
            *(float2*)&C[row0 * (size_t)N + col0] =
                make_float2(acc[im][jn][0], acc[im][jn][1]);
            *(float2*)&C[(row0 + 8) * (size_t)N + col0] =
                make_float2(acc[im][jn][2], acc[im][jn][3]);
        }
    }
}

// ---------------- prepass: tf32-rna rounding (+ zero padding) ---------------
__device__ __forceinline__ float4 round4(float4 v) {
    return make_float4(roundtf(v.x), roundtf(v.y), roundtf(v.z), roundtf(v.w));
}

__global__ void round_copy_k(const float* __restrict__ src, float* __restrict__ dst, long n4)
{
    long i = (long)blockIdx.x * blockDim.x + threadIdx.x;
    if (i >= n4) return;
    *(float4*)(dst + i * 4) = round4(*(const float4*)(src + i * 4));
}

// dst: [rows_pad x cols]; src: [rows_src x cols]; pad rows zero-filled.
__global__ void round_pad_rows_k(const float* __restrict__ src, float* __restrict__ dst,
                                 int rows_src, int cols, long n4)
{
    long i = (long)blockIdx.x * blockDim.x + threadIdx.x;
    if (i >= n4) return;
    long e = i * 4;
    int row = (int)(e / cols);
    float4 v = make_float4(0.f, 0.f, 0.f, 0.f);
    if (row < rows_src)
        v = round4(*(const float4*)(src + (size_t)row * cols + (e % cols)));
    *(float4*)(dst + e) = v;
}

// dst: [rows x cols_pad]; src: [rows x cols_src]; pad cols zero-filled.
// cols_src and cols_pad both divisible by 4 -> no float4 straddles the edge.
__global__ void round_pad_cols_k(const float* __restrict__ src, float* __restrict__ dst,
                                 int cols_src, int cols_pad, long n4)
{
    long i = (long)blockIdx.x * blockDim.x + threadIdx.x;
    if (i >= n4) return;
    long e = i * 4;
    int row = (int)(e / cols_pad);
    int col = (int)(e % cols_pad);
    float4 v = make_float4(0.f, 0.f, 0.f, 0.f);
    if (col < cols_src)
        v = round4(*(const float4*)(src + (size_t)row * cols_src + col));
    *(float4*)(dst + e) = v;
}

// ---------------- combine: cumsum/silu/delta + closed-form Hadamard ---------
// Operates on the padded layout; pad lanes are exactly 0 -> output 0.
__global__ void combine_kernel()
{
    const size_t total  = (size_t)BSROWS * INTER_PAD;
    const size_t stride = total;
    size_t idx = (size_t)blockIdx.x * blockDim.x + threadIdx.x;
    if (idx >= total) return;

    float gv[TSTEPS], uv[TSTEPS];
    #pragma unroll
    for (int t = 0; t < TSTEPS; ++t) {
        gv[t] = g_G[idx + (size_t)t * stride];
        uv[t] = g_U[idx + (size_t)t * stride];
    }

    float X = 0.f, Yprev = 0.f, SB = 0.f;
    float Av[TSTEPS];
    #pragma unroll
    for (int t = 0; t < TSTEPS; ++t) {
        X += gv[t];
        const float Y = X / (1.f + expf(-X));  // silu
        Av[t] = Y - Yprev;
        Yprev = Y;
        SB += uv[t];
    }
    const float SA = Yprev;  // telescoping: sum_t A[t] = Y[T-1]

    #pragma unroll
    for (int t = 0; t < TSTEPS; ++t)
        g_G[idx + (size_t)t * stride] = roundtf(0.5f * (Av[t] * SB + uv[t] * SA));
}

// ---------------- launch -----------------------------------------------------
extern "C" void kernel_launch(void* const* d_in, const int* in_sizes, int n_in,
                              void* d_out, int out_size)
{
    const float* x      = (const float*)d_in[0];
    const float* w_gate = (const float*)d_in[1];
    const float* w_up   = (const float*)d_in[2];
    const float* w_down = (const float*)d_in[3];
    float* out = (float*)d_out;
    (void)in_sizes; (void)n_in; (void)out_size;

    float *dX, *dWG, *dWU, *dWD, *dG, *dU;
    cudaGetSymbolAddress((void**)&dX,  g_X);
    cudaGetSymbolAddress((void**)&dWG, g_WG);
    cudaGetSymbolAddress((void**)&dWU, g_WU);
    cudaGetSymbolAddress((void**)&dWD, g_WD);
    cudaGetSymbolAddress((void**)&dG,  g_G);
    cudaGetSymbolAddress((void**)&dU,  g_U);

    cudaFuncSetAttribute(gemm_tn, cudaFuncAttributeMaxDynamicSharedMemorySize, DYN_SMEM);

    // Prepass: tf32-rna round (and zero-pad weights to INTER_PAD).
    {
        long n4 = (long)MROWS * HIDDEN / 4;
        round_copy_k<<<(unsigned)((n4 + 255) / 256), 256>>>(x, dX, n4);
        long w4 = (long)INTER_PAD * HIDDEN / 4;
        round_pad_rows_k<<<(unsigned)((w4 + 255) / 256), 256>>>(w_gate, dWG, INTER, HIDDEN, w4);
        round_pad_rows_k<<<(unsigned)((w4 + 255) / 256), 256>>>(w_up,   dWU, INTER, HIDDEN, w4);
        long d4 = (long)HIDDEN * INTER_PAD / 4;
        round_pad_cols_k<<<(unsigned)((d4 + 255) / 256), 256>>>(w_down, dWD, INTER, INTER_PAD, d4);
    }

    // Gate / up projections: (4096 x 5632) = x(4096x2048) @ W^T
    {
        dim3 grid(INTER_PAD / 256, MROWS / 128);   // 22 x 32
        gemm_tn<<<grid, 256, DYN_SMEM>>>(dX, dWG, dG, HIDDEN, INTER_PAD);
        gemm_tn<<<grid, 256, DYN_SMEM>>>(dX, dWU, dU, HIDDEN, INTER_PAD);
    }

    // Combine (C -> g_G, rounded for the next GEMM).
    {
        size_t total = (size_t)BSROWS * INTER_PAD;
        combine_kernel<<<(unsigned)((total + 255) / 256), 256>>>();
    }

    // Down projection: (4096 x 2048) = C(4096x5632) @ w_down'^T
    {
        dim3 grid(HIDDEN / 256, MROWS / 128);      // 8 x 32
        gemm_tn<<<grid, 256, DYN_SMEM>>>(dG, dWD, out, INTER_PAD, HIDDEN);
    }
}

// round 8
// speedup vs baseline: 4.1570x; 1.8521x over previous
#include <cuda_runtime.h>
#include <cuda_fp16.h>
#include <cstdint>

#define HIDDEN    2048
#define INTER     5504
#define INTER_PAD 5632   /* 22 * 256 */
#define TSTEPS    4
#define MROWS     4096   /* T*BSZ*SEQ */
#define BSROWS    1024   /* BSZ*SEQ */

#define KTILE     64     /* fp16 K-elements per tile: 128B rows */
#define BUF_BYTES 49152  /* A 16KB + B 32KB */
#define DYN_SMEM  (2 * BUF_BYTES)

// ---------------- scratch (device globals; no allocation allowed) ----------
__device__ __half g_X [(size_t)MROWS * HIDDEN];
__device__ __half g_WG[(size_t)INTER_PAD * HIDDEN];
__device__ __half g_WU[(size_t)INTER_PAD * HIDDEN];
__device__ __half g_WD[(size_t)HIDDEN * INTER_PAD];
__device__ float  g_G [(size_t)MROWS * INTER_PAD];
__device__ float  g_U [(size_t)MROWS * INTER_PAD];
__device__ __half g_C [(size_t)MROWS * INTER_PAD];

// ---------------- helpers ----------------------------------------------------
__device__ __forceinline__ uint32_t smem_u32(const void* p) {
    uint32_t a;
    asm("{ .reg .u64 t; cvta.to.shared.u64 t, %1; cvt.u32.u64 %0, t; }" : "=r"(a) : "l"(p));
    return a;
}

// ldmatrix x4 (b16): thread gets word (lane%4) of row (lane/4) per 8x8 matrix.
#define LDSM_X4(r0, r1, r2, r3, addr) \
    asm volatile("ldmatrix.sync.aligned.m8n8.x4.shared.b16 {%0,%1,%2,%3}, [%4];" \
                 : "=r"(r0), "=r"(r1), "=r"(r2), "=r"(r3) : "r"(addr))

__device__ __forceinline__ void mma_f16(float* d, const uint32_t* a, const uint32_t* b) {
    asm volatile(
        "mma.sync.aligned.m16n8k16.row.col.f32.f16.f16.f32 "
        "{%0,%1,%2,%3}, {%4,%5,%6,%7}, {%8,%9}, {%0,%1,%2,%3};\n"
        : "+f"(d[0]), "+f"(d[1]), "+f"(d[2]), "+f"(d[3])
        : "r"(a[0]), "r"(a[1]), "r"(a[2]), "r"(a[3]), "r"(b[0]), "r"(b[1]));
}

// ---------------- GEMM: C[m,n] = sum_k A[m,k]*B[n,k] ------------------------
// A: M x K row-major fp16, B: N x K row-major fp16, C: M x N row-major fp32.
// Block tile 128x256, 256 threads, 8 warps (2x4), warp tile 64x64.
// Register-prefetched globals, double-buffered smem, one barrier per K-tile,
// ldmatrix fragment loads, m16n8k16 fp16 MMA with fp32 accumulation.
// Requires M%128==0, N%256==0, K%64==0.
__global__ void __launch_bounds__(256, 1)
gemm_tn(const __half* __restrict__ A, const __half* __restrict__ B,
        float* __restrict__ C, int K, int N)
{
    extern __shared__ __align__(16) uint8_t smraw[];
    uint4* sm = reinterpret_cast<uint4*>(smraw);
    const uint32_t sb = smem_u32(smraw);

    const int tid  = threadIdx.x;
    const int lane = tid & 31;
    const int warp = tid >> 5;
    const int wm   = warp & 1;   // 2 warp rows of 64
    const int wn   = warp >> 1;  // 4 warp cols of 64

    // global-load mapping: 16B atoms, 8 per 128B (64-half) row chunk
    const int r = tid >> 3;      // 0..31 : row within group of 32
    const int c = tid & 7;       // 0..7  : 16B (k8) atom within row chunk

    // LDSM per-lane selectors (same algebra as tf32 version, k4 -> k8 atoms):
    //  A matrices: m = base + [0|8] + lane&7, k8 = ks*2 + lane>>4
    //  B matrices: n = base + [0|8] + lane&7, k8 = ks*2 + (lane>>3)&1
    const int rsel   = lane & 7;
    const int a_k8hi = lane >> 4;
    const int a_moff = ((lane >> 3) & 1) << 3;
    const int b_k8lo = (lane >> 3) & 1;
    const int b_noff = (lane >> 4) << 3;
    const int mrowA  = wm * 64 + a_moff + rsel;
    const int nrowB  = wn * 64 + b_noff + rsel;

    const size_t mBase = (size_t)blockIdx.y * 128;
    const size_t nBase = (size_t)blockIdx.x * 256;
    const int NK = K / KTILE;

    const __half* Ag = A + (mBase + (size_t)r) * (size_t)K + (size_t)c * 8;
    const __half* Bg = B + (nBase + (size_t)r) * (size_t)K + (size_t)c * 8;

    uint4 pa[4], pb[8];

    auto ldg_tile = [&](int kt) {
        const __half* Ak = Ag + (size_t)kt * KTILE;
        const __half* Bk = Bg + (size_t)kt * KTILE;
        #pragma unroll
        for (int j = 0; j < 4; ++j)
            pa[j] = *(const uint4*)(Ak + (size_t)(j * 32) * K);
        #pragma unroll
        for (int j = 0; j < 8; ++j)
            pb[j] = *(const uint4*)(Bk + (size_t)(j * 32) * K);
    };
    // smem buffer: A atoms [k8(0..7)][m(0..127)] uint4 at slot m^k8;
    //              B atoms [k8(0..7)][n(0..255)] uint4 at slot n^k8 (at +16KB).
    auto sts_tile = [&](int buf) {
        uint4* As = sm + buf * (BUF_BYTES / 16);
        uint4* Bs = As + 1024;
        #pragma unroll
        for (int j = 0; j < 4; ++j) {
            const int m = j * 32 + r;
            As[c * 128 + (m ^ c)] = pa[j];
        }
        #pragma unroll
        for (int j = 0; j < 8; ++j) {
            const int n = j * 32 + r;
            Bs[c * 256 + (n ^ c)] = pb[j];
        }
    };

    float acc[4][8][4];
    #pragma unroll
    for (int i = 0; i < 4; ++i)
        #pragma unroll
        for (int j = 0; j < 8; ++j)
            #pragma unroll
            for (int q = 0; q < 4; ++q) acc[i][j][q] = 0.f;

    // prologue
    ldg_tile(0);
    sts_tile(0);
    if (NK > 1) ldg_tile(1);
    __syncthreads();

    for (int kt = 0; kt < NK; ++kt) {
        if (kt + 1 < NK) {
            sts_tile((kt + 1) & 1);
            if (kt + 2 < NK) ldg_tile(kt + 2);
        }

        const uint32_t abase = sb + (uint32_t)((kt & 1) * BUF_BYTES);
        const uint32_t bbase = abase + 16384;

        #pragma unroll
        for (int ks = 0; ks < 4; ++ks) {        // 4 k16-steps over 64-K tile
            const uint32_t ak8 = (uint32_t)(ks * 2 + a_k8hi);
            const uint32_t bk8 = (uint32_t)(ks * 2 + b_k8lo);

            uint32_t af[4][4];
            #pragma unroll
            for (int im = 0; im < 4; ++im) {
                const uint32_t m = (uint32_t)(mrowA + im * 16);
                const uint32_t addr = abase + (ak8 << 11) + (((m ^ ak8) & 127u) << 4);
                LDSM_X4(af[im][0], af[im][1], af[im][2], af[im][3], addr);
            }
            uint32_t bf[8][2];
            #pragma unroll
            for (int p = 0; p < 4; ++p) {
                const uint32_t n = (uint32_t)(nrowB + p * 16);
                const uint32_t addr = bbase + (bk8 << 12) + (((n ^ bk8) & 255u) << 4);
                LDSM_X4(bf[2 * p][0], bf[2 * p][1], bf[2 * p + 1][0], bf[2 * p + 1][1], addr);
            }
            #pragma unroll
            for (int im = 0; im < 4; ++im)
                #pragma unroll
                for (int jn = 0; jn < 8; ++jn)
                    mma_f16(acc[im][jn], af[im], bf[jn]);
        }
        __syncthreads();
    }

    // Epilogue: fragment layout -> global fp32 (float2 per half-row).
    const int g  = lane >> 2;
    const int q2 = (lane & 3) * 2;
    #pragma unroll
    for (int im = 0; im < 4; ++im) {
        const size_t row0 = mBase + wm * 64 + im * 16 + g;
        #pragma unroll
        for (int jn = 0; jn < 8; ++jn) {
            const size_t col0 = nBase + wn * 64 + jn * 8 + q2;
            *(float2*)&C[row0 * (size_t)N + col0] =
                make_float2(acc[im][jn][0], acc[im][jn][1]);
            *(float2*)&C[(row0 + 8) * (size_t)N + col0] =
                make_float2(acc[im][jn][2], acc[im][jn][3]);
        }
    }
}

// ---------------- prepass: fp32 -> fp16 (rn) conversion (+ zero padding) ----
__device__ __forceinline__ void store_h4(__half* dst, float4 v) {
    __half2* d2 = reinterpret_cast<__half2*>(dst);
    d2[0] = __floats2half2_rn(v.x, v.y);
    d2[1] = __floats2half2_rn(v.z, v.w);
}

__global__ void h_copy_k(const float* __restrict__ src, __half* __restrict__ dst, long n4)
{
    long i = (long)blockIdx.x * blockDim.x + threadIdx.x;
    if (i >= n4) return;
    store_h4(dst + i * 4, *(const float4*)(src + i * 4));
}

// dst: [rows_pad x cols]; src: [rows_src x cols]; pad rows zero-filled.
__global__ void h_pad_rows_k(const float* __restrict__ src, __half* __restrict__ dst,
                             int rows_src, int cols, long n4)
{
    long i = (long)blockIdx.x * blockDim.x + threadIdx.x;
    if (i >= n4) return;
    long e = i * 4;
    int row = (int)(e / cols);
    float4 v = make_float4(0.f, 0.f, 0.f, 0.f);
    if (row < rows_src)
        v = *(const float4*)(src + (size_t)row * cols + (e % cols));
    store_h4(dst + e, v);
}

// dst: [rows x cols_pad]; src: [rows x cols_src]; both cols divisible by 4.
__global__ void h_pad_cols_k(const float* __restrict__ src, __half* __restrict__ dst,
                             int cols_src, int cols_pad, long n4)
{
    long i = (long)blockIdx.x * blockDim.x + threadIdx.x;
    if (i >= n4) return;
    long e = i * 4;
    int row = (int)(e / cols_pad);
    int col = (int)(e % cols_pad);
    float4 v = make_float4(0.f, 0.f, 0.f, 0.f);
    if (col < cols_src)
        v = *(const float4*)(src + (size_t)row * cols_src + col);
    store_h4(dst + e, v);
}

// ---------------- combine: cumsum/silu/delta + closed-form Hadamard ---------
// Reads fp32 G/U, writes fp16 C operand (pad lanes are exactly 0 -> 0).
__global__ void combine_kernel()
{
    const size_t total  = (size_t)BSROWS * INTER_PAD;
    const size_t stride = total;
    size_t idx = (size_t)blockIdx.x * blockDim.x + threadIdx.x;
    if (idx >= total) return;

    float gv[TSTEPS], uv[TSTEPS];
    #pragma unroll
    for (int t = 0; t < TSTEPS; ++t) {
        gv[t] = g_G[idx + (size_t)t * stride];
        uv[t] = g_U[idx + (size_t)t * stride];
    }

    float X = 0.f, Yprev = 0.f, SB = 0.f;
    float Av[TSTEPS];
    #pragma unroll
    for (int t = 0; t < TSTEPS; ++t) {
        X += gv[t];
        const float Y = X / (1.f + expf(-X));  // silu
        Av[t] = Y - Yprev;
        Yprev = Y;
        SB += uv[t];
    }
    const float SA = Yprev;  // telescoping: sum_t A[t] = Y[T-1]

    #pragma unroll
    for (int t = 0; t < TSTEPS; ++t)
        g_C[idx + (size_t)t * stride] =
            __float2half_rn(0.5f * (Av[t] * SB + uv[t] * SA));
}

// ---------------- launch -----------------------------------------------------
extern "C" void kernel_launch(void* const* d_in, const int* in_sizes, int n_in,
                              void* d_out, int out_size)
{
    const float* x      = (const float*)d_in[0];
    const float* w_gate = (const float*)d_in[1];
    const float* w_up   = (const float*)d_in[2];
    const float* w_down = (const float*)d_in[3];
    float* out = (float*)d_out;
    (void)in_sizes; (void)n_in; (void)out_size;

    __half *dX, *dWG, *dWU, *dWD, *dC;
    float *dG, *dU;
    cudaGetSymbolAddress((void**)&dX,  g_X);
    cudaGetSymbolAddress((void**)&dWG, g_WG);
    cudaGetSymbolAddress((void**)&dWU, g_WU);
    cudaGetSymbolAddress((void**)&dWD, g_WD);
    cudaGetSymbolAddress((void**)&dG,  g_G);
    cudaGetSymbolAddress((void**)&dU,  g_U);
    cudaGetSymbolAddress((void**)&dC,  g_C);

    cudaFuncSetAttribute(gemm_tn, cudaFuncAttributeMaxDynamicSharedMemorySize, DYN_SMEM);

    // Prepass: fp32 -> fp16 (and zero-pad weights to INTER_PAD).
    {
        long n4 = (long)MROWS * HIDDEN / 4;
        h_copy_k<<<(unsigned)((n4 + 255) / 256), 256>>>(x, dX, n4);
        long w4 = (long)INTER_PAD * HIDDEN / 4;
        h_pad_rows_k<<<(unsigned)((w4 + 255) / 256), 256>>>(w_gate, dWG, INTER, HIDDEN, w4);
        h_pad_rows_k<<<(unsigned)((w4 + 255) / 256), 256>>>(w_up,   dWU, INTER, HIDDEN, w4);
        long d4 = (long)HIDDEN * INTER_PAD / 4;
        h_pad_cols_k<<<(unsigned)((d4 + 255) / 256), 256>>>(w_down, dWD, INTER, INTER_PAD, d4);
    }

    // Gate / up projections: (4096 x 5632) = x(4096x2048) @ W^T
    {
        dim3 grid(INTER_PAD / 256, MROWS / 128);   // 22 x 32
        gemm_tn<<<grid, 256, DYN_SMEM>>>(dX, dWG, dG, HIDDEN, INTER_PAD);
        gemm_tn<<<grid, 256, DYN_SMEM>>>(dX, dWU, dU, HIDDEN, INTER_PAD);
    }

    // Combine (fp32 G/U -> fp16 C operand).
    {
        size_t total = (size_t)BSROWS * INTER_PAD;
        combine_kernel<<<(unsigned)((total + 255) / 256), 256>>>();
    }

    // Down projection: (4096 x 2048) = C(4096x5632) @ w_down'^T
    {
        dim3 grid(HIDDEN / 256, MROWS / 128);      // 8 x 32
        gemm_tn<<<grid, 256, DYN_SMEM>>>(dC, dWD, out, INTER_PAD, HIDDEN);
    }
}

// round 9
// speedup vs baseline: 4.1889x; 1.0077x over previous
#include <cuda_runtime.h>
#include <cuda_fp16.h>
#include <cstdint>

#define HIDDEN    2048
#define INTER     5504
#define INTER_PAD 5632            /* 22 * 256 */
#define NFUSED    (2 * INTER_PAD) /* gate+up concatenated: 11264 = 44*256 */
#define TSTEPS    4
#define MROWS     4096            /* T*BSZ*SEQ */
#define BSROWS    1024            /* BSZ*SEQ */

#define KTILE     64              /* fp16 K-elements per tile: 128B rows */
#define BUF_BYTES 49152           /* A 16KB + B 32KB */
#define DYN_SMEM  (2 * BUF_BYTES)

// ---------------- scratch (device globals; no allocation allowed) ----------
__device__ __half g_X  [(size_t)MROWS * HIDDEN];
__device__ __half g_WGU[(size_t)NFUSED * HIDDEN];     /* rows 0..5631 gate, 5632.. up */
__device__ __half g_WD [(size_t)HIDDEN * INTER_PAD];
__device__ __half g_GU [(size_t)MROWS * NFUSED];      /* fused gate/up outputs, fp16 */
__device__ __half g_C  [(size_t)MROWS * INTER_PAD];   /* combine output, fp16 */

// ---------------- helpers ----------------------------------------------------
__device__ __forceinline__ uint32_t smem_u32(const void* p) {
    uint32_t a;
    asm("{ .reg .u64 t; cvta.to.shared.u64 t, %1; cvt.u32.u64 %0, t; }" : "=r"(a) : "l"(p));
    return a;
}

// ldmatrix x4 (b16): thread gets word (lane%4) of row (lane/4) per 8x8 matrix.
#define LDSM_X4(r0, r1, r2, r3, addr) \
    asm volatile("ldmatrix.sync.aligned.m8n8.x4.shared.b16 {%0,%1,%2,%3}, [%4];" \
                 : "=r"(r0), "=r"(r1), "=r"(r2), "=r"(r3) : "r"(addr))

__device__ __forceinline__ void mma_f16(float* d, const uint32_t* a, const uint32_t* b) {
    asm volatile(
        "mma.sync.aligned.m16n8k16.row.col.f32.f16.f16.f32 "
        "{%0,%1,%2,%3}, {%4,%5,%6,%7}, {%8,%9}, {%0,%1,%2,%3};\n"
        : "+f"(d[0]), "+f"(d[1]), "+f"(d[2]), "+f"(d[3])
        : "r"(a[0]), "r"(a[1]), "r"(a[2]), "r"(a[3]), "r"(b[0]), "r"(b[1]));
}

// ---------------- GEMM: C[m,n] = sum_k A[m,k]*B[n,k] ------------------------
// A: M x K row-major fp16, B: N x K row-major fp16.
// OutT = float (fp32 store) or __half (fp16 store).
// Block tile 128x256, 256 threads, 8 warps (2x4), warp tile 64x64.
// Register-prefetched globals, double-buffered smem, one barrier per K-tile,
// ldmatrix fragment loads, m16n8k16 fp16 MMA with fp32 accumulation.
// Requires M%128==0, N%256==0, K%64==0.
template <typename OutT>
__global__ void __launch_bounds__(256, 1)
gemm_tn(const __half* __restrict__ A, const __half* __restrict__ B,
        OutT* __restrict__ C, int K, int N)
{
    extern __shared__ __align__(16) uint8_t smraw[];
    uint4* sm = reinterpret_cast<uint4*>(smraw);
    const uint32_t sb = smem_u32(smraw);

    const int tid  = threadIdx.x;
    const int lane = tid & 31;
    const int warp = tid >> 5;
    const int wm   = warp & 1;   // 2 warp rows of 64
    const int wn   = warp >> 1;  // 4 warp cols of 64

    // global-load mapping: 16B atoms, 8 per 128B (64-half) row chunk
    const int r = tid >> 3;      // 0..31 : row within group of 32
    const int c = tid & 7;       // 0..7  : 16B (k8) atom within row chunk

    // LDSM per-lane selectors (verified bit-exact since R4):
    const int rsel   = lane & 7;
    const int a_k8hi = lane >> 4;
    const int a_moff = ((lane >> 3) & 1) << 3;
    const int b_k8lo = (lane >> 3) & 1;
    const int b_noff = (lane >> 4) << 3;
    const int mrowA  = wm * 64 + a_moff + rsel;
    const int nrowB  = wn * 64 + b_noff + rsel;

    const size_t mBase = (size_t)blockIdx.y * 128;
    const size_t nBase = (size_t)blockIdx.x * 256;
    const int NK = K / KTILE;

    const __half* Ag = A + (mBase + (size_t)r) * (size_t)K + (size_t)c * 8;
    const __half* Bg = B + (nBase + (size_t)r) * (size_t)K + (size_t)c * 8;

    uint4 pa[4], pb[8];

    auto ldg_tile = [&](int kt) {
        const __half* Ak = Ag + (size_t)kt * KTILE;
        const __half* Bk = Bg + (size_t)kt * KTILE;
        #pragma unroll
        for (int j = 0; j < 4; ++j)
            pa[j] = *(const uint4*)(Ak + (size_t)(j * 32) * K);
        #pragma unroll
        for (int j = 0; j < 8; ++j)
            pb[j] = *(const uint4*)(Bk + (size_t)(j * 32) * K);
    };
    // smem buffer: A atoms [k8(0..7)][m(0..127)] uint4 at slot m^k8;
    //              B atoms [k8(0..7)][n(0..255)] uint4 at slot n^k8 (at +16KB).
    auto sts_tile = [&](int buf) {
        uint4* As = sm + buf * (BUF_BYTES / 16);
        uint4* Bs = As + 1024;
        #pragma unroll
        for (int j = 0; j < 4; ++j) {
            const int m = j * 32 + r;
            As[c * 128 + (m ^ c)] = pa[j];
        }
        #pragma unroll
        for (int j = 0; j < 8; ++j) {
            const int n = j * 32 + r;
            Bs[c * 256 + (n ^ c)] = pb[j];
        }
    };

    float acc[4][8][4];
    #pragma unroll
    for (int i = 0; i < 4; ++i)
        #pragma unroll
        for (int j = 0; j < 8; ++j)
            #pragma unroll
            for (int q = 0; q < 4; ++q) acc[i][j][q] = 0.f;

    // prologue
    ldg_tile(0);
    sts_tile(0);
    if (NK > 1) ldg_tile(1);
    __syncthreads();

    for (int kt = 0; kt < NK; ++kt) {
        if (kt + 1 < NK) {
            sts_tile((kt + 1) & 1);
            if (kt + 2 < NK) ldg_tile(kt + 2);
        }

        const uint32_t abase = sb + (uint32_t)((kt & 1) * BUF_BYTES);
        const uint32_t bbase = abase + 16384;

        #pragma unroll
        for (int ks = 0; ks < 4; ++ks) {        // 4 k16-steps over 64-K tile
            const uint32_t ak8 = (uint32_t)(ks * 2 + a_k8hi);
            const uint32_t bk8 = (uint32_t)(ks * 2 + b_k8lo);

            uint32_t af[4][4];
            #pragma unroll
            for (int im = 0; im < 4; ++im) {
                const uint32_t m = (uint32_t)(mrowA + im * 16);
                const uint32_t addr = abase + (ak8 << 11) + (((m ^ ak8) & 127u) << 4);
                LDSM_X4(af[im][0], af[im][1], af[im][2], af[im][3], addr);
            }
            uint32_t bf[8][2];
            #pragma unroll
            for (int p = 0; p < 4; ++p) {
                const uint32_t n = (uint32_t)(nrowB + p * 16);
                const uint32_t addr = bbase + (bk8 << 12) + (((n ^ bk8) & 255u) << 4);
                LDSM_X4(bf[2 * p][0], bf[2 * p][1], bf[2 * p + 1][0], bf[2 * p + 1][1], addr);
            }
            #pragma unroll
            for (int im = 0; im < 4; ++im)
                #pragma unroll
                for (int jn = 0; jn < 8; ++jn)
                    mma_f16(acc[im][jn], af[im], bf[jn]);
        }
        __syncthreads();
    }

    // Epilogue: fragment layout -> global (pair of cols per quad-lane).
    const int g  = lane >> 2;
    const int q2 = (lane & 3) * 2;
    #pragma unroll
    for (int im = 0; im < 4; ++im) {
        const size_t row0 = mBase + wm * 64 + im * 16 + g;
        #pragma unroll
        for (int jn = 0; jn < 8; ++jn) {
            const size_t col0 = nBase + wn * 64 + jn * 8 + q2;
            if constexpr (sizeof(OutT) == 4) {
                *(float2*)&C[row0 * (size_t)N + col0] =
                    make_float2(acc[im][jn][0], acc[im][jn][1]);
                *(float2*)&C[(row0 + 8) * (size_t)N + col0] =
                    make_float2(acc[im][jn][2], acc[im][jn][3]);
            } else {
                *(__half2*)&C[row0 * (size_t)N + col0] =
                    __floats2half2_rn(acc[im][jn][0], acc[im][jn][1]);
                *(__half2*)&C[(row0 + 8) * (size_t)N + col0] =
                    __floats2half2_rn(acc[im][jn][2], acc[im][jn][3]);
            }
        }
    }
}

// ---------------- prepass: fp32 -> fp16 (rn) conversion (+ zero padding) ----
__device__ __forceinline__ void store_h4(__half* dst, float4 v) {
    __half2* d2 = reinterpret_cast<__half2*>(dst);
    d2[0] = __floats2half2_rn(v.x, v.y);
    d2[1] = __floats2half2_rn(v.z, v.w);
}

__global__ void h_copy_k(const float* __restrict__ src, __half* __restrict__ dst, long n4)
{
    long i = (long)blockIdx.x * blockDim.x + threadIdx.x;
    if (i >= n4) return;
    store_h4(dst + i * 4, *(const float4*)(src + i * 4));
}

// dst: [rows_pad x cols]; src: [rows_src x cols]; pad rows zero-filled.
__global__ void h_pad_rows_k(const float* __restrict__ src, __half* __restrict__ dst,
                             int rows_src, int cols, long n4)
{
    long i = (long)blockIdx.x * blockDim.x + threadIdx.x;
    if (i >= n4) return;
    long e = i * 4;
    int row = (int)(e / cols);
    float4 v = make_float4(0.f, 0.f, 0.f, 0.f);
    if (row < rows_src)
        v = *(const float4*)(src + (size_t)row * cols + (e % cols));
    store_h4(dst + e, v);
}

// dst: [rows x cols_pad]; src: [rows x cols_src]; both cols divisible by 4.
__global__ void h_pad_cols_k(const float* __restrict__ src, __half* __restrict__ dst,
                             int cols_src, int cols_pad, long n4)
{
    long i = (long)blockIdx.x * blockDim.x + threadIdx.x;
    if (i >= n4) return;
    long e = i * 4;
    int row = (int)(e / cols_pad);
    int col = (int)(e % cols_pad);
    float4 v = make_float4(0.f, 0.f, 0.f, 0.f);
    if (col < cols_src)
        v = *(const float4*)(src + (size_t)row * cols_src + col);
    store_h4(dst + e, v);
}

// ---------------- combine: cumsum/silu/delta + closed-form Hadamard ---------
// Reads fp16 fused GU (gate at col i, up at col INTER_PAD+i), computes in fp32,
// writes fp16 C operand. Pad lanes are exactly 0 -> output 0.
__global__ void combine_kernel()
{
    const size_t total = (size_t)BSROWS * INTER_PAD;
    size_t idx = (size_t)blockIdx.x * blockDim.x + threadIdx.x;
    if (idx >= total) return;

    const size_t row = idx / INTER_PAD;       // 0..BSROWS-1
    const size_t col = idx % INTER_PAD;
    const size_t rstride = (size_t)BSROWS * NFUSED;   // t-slab stride in GU

    float gv[TSTEPS], uv[TSTEPS];
    #pragma unroll
    for (int t = 0; t < TSTEPS; ++t) {
        const size_t base = (size_t)t * rstride + row * NFUSED;
        gv[t] = __half2float(g_GU[base + col]);
        uv[t] = __half2float(g_GU[base + INTER_PAD + col]);
    }

    float X = 0.f, Yprev = 0.f, SB = 0.f;
    float Av[TSTEPS];
    #pragma unroll
    for (int t = 0; t < TSTEPS; ++t) {
        X += gv[t];
        const float Y = X / (1.f + expf(-X));  // silu
        Av[t] = Y - Yprev;
        Yprev = Y;
        SB += uv[t];
    }
    const float SA = Yprev;  // telescoping: sum_t A[t] = Y[T-1]

    const size_t cstride = (size_t)BSROWS * INTER_PAD;
    #pragma unroll
    for (int t = 0; t < TSTEPS; ++t)
        g_C[idx + (size_t)t * cstride] =
            __float2half_rn(0.5f * (Av[t] * SB + uv[t] * SA));
}

// ---------------- launch -----------------------------------------------------
extern "C" void kernel_launch(void* const* d_in, const int* in_sizes, int n_in,
                              void* d_out, int out_size)
{
    const float* x      = (const float*)d_in[0];
    const float* w_gate = (const float*)d_in[1];
    const float* w_up   = (const float*)d_in[2];
    const float* w_down = (const float*)d_in[3];
    float* out = (float*)d_out;
    (void)in_sizes; (void)n_in; (void)out_size;

    __half *dX, *dWGU, *dWD, *dGU, *dC;
    cudaGetSymbolAddress((void**)&dX,   g_X);
    cudaGetSymbolAddress((void**)&dWGU, g_WGU);
    cudaGetSymbolAddress((void**)&dWD,  g_WD);
    cudaGetSymbolAddress((void**)&dGU,  g_GU);
    cudaGetSymbolAddress((void**)&dC,   g_C);

    cudaFuncSetAttribute(gemm_tn<__half>, cudaFuncAttributeMaxDynamicSharedMemorySize, DYN_SMEM);
    cudaFuncSetAttribute(gemm_tn<float>,  cudaFuncAttributeMaxDynamicSharedMemorySize, DYN_SMEM);

    // Prepass: fp32 -> fp16 (weights zero-padded to INTER_PAD; gate/up concat).
    {
        long n4 = (long)MROWS * HIDDEN / 4;
        h_copy_k<<<(unsigned)((n4 + 255) / 256), 256>>>(x, dX, n4);
        long w4 = (long)INTER_PAD * HIDDEN / 4;
        h_pad_rows_k<<<(unsigned)((w4 + 255) / 256), 256>>>(w_gate, dWGU, INTER, HIDDEN, w4);
        h_pad_rows_k<<<(unsigned)((w4 + 255) / 256), 256>>>(
            w_up, dWGU + (size_t)INTER_PAD * HIDDEN, INTER, HIDDEN, w4);
        long d4 = (long)HIDDEN * INTER_PAD / 4;
        h_pad_cols_k<<<(unsigned)((d4 + 255) / 256), 256>>>(w_down, dWD, INTER, INTER_PAD, d4);
    }

    // Fused gate+up projection: (4096 x 11264) = x(4096x2048) @ [WG;WU]^T -> fp16
    {
        dim3 grid(NFUSED / 256, MROWS / 128);      // 44 x 32
        gemm_tn<__half><<<grid, 256, DYN_SMEM>>>(dX, dWGU, dGU, HIDDEN, NFUSED);
    }

    // Combine (fp16 GU -> fp16 C operand).
    {
        size_t total = (size_t)BSROWS * INTER_PAD;
        combine_kernel<<<(unsigned)((total + 255) / 256), 256>>>();
    }

    // Down projection: (4096 x 2048) = C(4096x5632) @ w_down'^T -> fp32 out
    {
        dim3 grid(HIDDEN / 256, MROWS / 128);      // 8 x 32
        gemm_tn<float><<<grid, 256, DYN_SMEM>>>(dC, dWD, out, INTER_PAD, HIDDEN);
    }
}